// round 1
// baseline (speedup 1.0000x reference)
#include <cuda_runtime.h>
#include <cstdint>

#define ATT_SCALE 0.125f
#define BB 2
#define LL 8192
#define SSS 4096
#define DD 1024
#define HH 16
#define HKVN 4
#define HDIM 64
#define NBLK 512          // L / 16
#define KVW 256           // HKV * HD

// ---------------- scratch (device globals, no allocation) ----------------
__device__ float g_pooled[BB * NBLK * DD];
__device__ float g_q[BB * NBLK * DD];
__device__ float g_k[BB * SSS * KVW];
__device__ float g_v[BB * SSS * KVW];
__device__ float g_ob[BB * NBLK * DD];

// ---------------- 1) block-mean pooling ----------------
__global__ void pool_kernel(const float* __restrict__ x, float* __restrict__ pooled) {
    int row = blockIdx.x;                      // b*512 + blk
    const float* base = x + (size_t)row * 16 * DD;
    float* outp = pooled + (size_t)row * DD;
#pragma unroll
    for (int j = 0; j < 4; j++) {
        int col = threadIdx.x + j * 256;
        float s = 0.f;
#pragma unroll
        for (int t = 0; t < 16; t++) s += base[t * DD + col];
        outp[col] = s * 0.0625f;
    }
}

// ---------------- tiled SGEMM (fp32, ping-pong double buffered) ----------------
// C[M,N] = A[M,K] @ B[K,N], all row-major. 256 threads, 16x16 layout, TMxTN/thread.
// BCAST: C row m is broadcast to 16 output token rows (out-projection epilogue).
template <int BM, int BN, int TM, int TN, bool BCAST>
__global__ void __launch_bounds__(256)
sgemm_kernel(const float* __restrict__ A, const float* __restrict__ B,
             float* __restrict__ C, int M, int N, int K) {
    constexpr int BK = 8;
    __shared__ float As[2][BK][BM];
    __shared__ float Bs[2][BK][BN];

    const int tid = threadIdx.x;
    const int tx = tid & 15, ty = tid >> 4;
    const int m0 = blockIdx.y * BM, n0 = blockIdx.x * BN;

    constexpr int RA = BM * BK / 256;
    constexpr int RB = BN * BK / 256;
    float ra[RA], rb[RB];

    float acc[TM][TN];
#pragma unroll
    for (int i = 0; i < TM; i++)
#pragma unroll
        for (int j = 0; j < TN; j++) acc[i][j] = 0.f;

    // initial tile -> buffer 0
#pragma unroll
    for (int i = 0; i < RA; i++) {
        int e = i * 256 + tid; int r = e >> 3; int c = e & 7;
        As[0][c][r] = A[(size_t)(m0 + r) * K + c];
    }
#pragma unroll
    for (int i = 0; i < RB; i++) {
        int e = i * 256 + tid; int r = e / BN; int c = e % BN;
        Bs[0][r][c] = B[(size_t)r * N + n0 + c];
    }
    __syncthreads();

    const int nt = K / BK;
    for (int t = 0; t < nt; t++) {
        const int cur = t & 1;
        if (t + 1 < nt) {
            const int k0 = (t + 1) * BK;
#pragma unroll
            for (int i = 0; i < RA; i++) {
                int e = i * 256 + tid; int r = e >> 3; int c = e & 7;
                ra[i] = A[(size_t)(m0 + r) * K + k0 + c];
            }
#pragma unroll
            for (int i = 0; i < RB; i++) {
                int e = i * 256 + tid; int r = e / BN; int c = e % BN;
                rb[i] = B[(size_t)(k0 + r) * N + n0 + c];
            }
        }
#pragma unroll
        for (int kk = 0; kk < BK; kk++) {
            float av[TM], bv[TN];
#pragma unroll
            for (int i = 0; i < TM; i++) av[i] = As[cur][kk][ty * TM + i];
#pragma unroll
            for (int j = 0; j < TN; j++) bv[j] = Bs[cur][kk][tx * TN + j];
#pragma unroll
            for (int i = 0; i < TM; i++)
#pragma unroll
                for (int j = 0; j < TN; j++) acc[i][j] += av[i] * bv[j];
        }
        if (t + 1 < nt) {
            const int nxt = cur ^ 1;
#pragma unroll
            for (int i = 0; i < RA; i++) {
                int e = i * 256 + tid; int r = e >> 3; int c = e & 7;
                As[nxt][c][r] = ra[i];
            }
#pragma unroll
            for (int i = 0; i < RB; i++) {
                int e = i * 256 + tid; int r = e / BN; int c = e % BN;
                Bs[nxt][r][c] = rb[i];
            }
        }
        __syncthreads();
    }

    if (!BCAST) {
#pragma unroll
        for (int i = 0; i < TM; i++) {
            int m = m0 + ty * TM + i;
#pragma unroll
            for (int j = 0; j < TN; j += 4) {
                float4 vv = make_float4(acc[i][j], acc[i][j + 1], acc[i][j + 2], acc[i][j + 3]);
                *(float4*)&C[(size_t)m * N + n0 + tx * TN + j] = vv;
            }
        }
    } else {
        // m -> (b = m>>9, blk = m&511); broadcast to 16 token rows
#pragma unroll
        for (int i = 0; i < TM; i++) {
            int m = m0 + ty * TM + i;
            int bo = (m >> 9) * LL + (m & 511) * 16;
#pragma unroll
            for (int j = 0; j < TN; j += 4) {
                float4 vv = make_float4(acc[i][j], acc[i][j + 1], acc[i][j + 2], acc[i][j + 3]);
                for (int tt = 0; tt < 16; tt++)
                    *(float4*)&C[(size_t)(bo + tt) * N + n0 + tx * TN + j] = vv;
            }
        }
    }
}

// ---------------- flash attention (fused, online softmax) ----------------
// grid: (nb/64, H, B). 64 query-blocks x 64-key chunks x HD=64.
// smem: Qt/Kt transposed [d][row] stride 68 for conflict-free float4 LDS.
#define TSTR 68
__global__ void __launch_bounds__(256)
attn_kernel(const float* __restrict__ q, const float* __restrict__ k,
            const float* __restrict__ v, const int* __restrict__ mask,
            float* __restrict__ ob) {
    extern __shared__ float sm[];
    float* Qt  = sm;                    // [64][68] transposed: Qt[d][r]
    float* Kt  = sm + 64 * TSTR;        // [64][68] transposed: Kt[d][c]
    float* Vs  = sm + 2 * 64 * TSTR;    // [64][68] row-major: Vs[kc][j]
    float* St  = sm + 3 * 64 * TSTR;    // [64][68] transposed: St[c][r]
    float* m_s = sm + 4 * 64 * TSTR;    // [64]
    float* l_s = m_s + 64;              // [64]
    float* a_s = l_s + 64;              // [64] per-chunk alpha
    int*  mskv = (int*)(a_s + 64);      // [64]

    const int tid = threadIdx.x;
    const int tx = tid & 15, ty = tid >> 4;
    const int blk0 = blockIdx.x * 64;
    const int h = blockIdx.y;
    const int b = blockIdx.z;
    const int g = h >> 2;               // kv group (hpg = 4)

    // load Q tile transposed: Qt[c][r] = q[(b*512+blk0+r), h*64+c]
#pragma unroll
    for (int i = 0; i < 4; i++) {
        int e = i * 256 + tid;
        int r = e >> 4, c4 = (e & 15) * 4;
        float4 qv = *(const float4*)&q[(size_t)(b * NBLK + blk0 + r) * DD + h * HDIM + c4];
        Qt[(c4 + 0) * TSTR + r] = qv.x;
        Qt[(c4 + 1) * TSTR + r] = qv.y;
        Qt[(c4 + 2) * TSTR + r] = qv.z;
        Qt[(c4 + 3) * TSTR + r] = qv.w;
    }
    if (tid < 64) { m_s[tid] = -3.0e38f; l_s[tid] = 0.f; }

    float o[4][4];
#pragma unroll
    for (int i = 0; i < 4; i++)
#pragma unroll
        for (int j = 0; j < 4; j++) o[i][j] = 0.f;

    for (int s0 = 0; s0 < SSS; s0 += 64) {
        __syncthreads();   // prev chunk's PV done; (first iter: orders Q/m/l writes)
        // load K chunk (transposed) + V chunk + mask
#pragma unroll
        for (int i = 0; i < 4; i++) {
            int e = i * 256 + tid;
            int r = e >> 4, c4 = (e & 15) * 4;
            size_t goff = (size_t)(b * SSS + s0 + r) * KVW + g * HDIM + c4;
            float4 kv = *(const float4*)&k[goff];
            Kt[(c4 + 0) * TSTR + r] = kv.x;
            Kt[(c4 + 1) * TSTR + r] = kv.y;
            Kt[(c4 + 2) * TSTR + r] = kv.z;
            Kt[(c4 + 3) * TSTR + r] = kv.w;
            float4 vv = *(const float4*)&v[goff];
            *(float4*)&Vs[r * TSTR + c4] = vv;
        }
        if (tid < 64) mskv[tid] = mask[b * SSS + s0 + tid];
        __syncthreads();

        // S = Q @ K^T  (4x4 per thread: rows ty*4.., cols tx*4..)
        float s[4][4];
#pragma unroll
        for (int i = 0; i < 4; i++)
#pragma unroll
            for (int j = 0; j < 4; j++) s[i][j] = 0.f;
#pragma unroll 8
        for (int kd = 0; kd < 64; kd++) {
            float4 aq = *(const float4*)&Qt[kd * TSTR + ty * 4];
            float4 bk = *(const float4*)&Kt[kd * TSTR + tx * 4];
            float av[4] = {aq.x, aq.y, aq.z, aq.w};
            float bv[4] = {bk.x, bk.y, bk.z, bk.w};
#pragma unroll
            for (int i = 0; i < 4; i++)
#pragma unroll
                for (int j = 0; j < 4; j++) s[i][j] += av[i] * bv[j];
        }
#pragma unroll
        for (int j = 0; j < 4; j++) {
            int c = tx * 4 + j;
            bool ok = mskv[c] != 0;
#pragma unroll
            for (int i = 0; i < 4; i++)
                St[c * TSTR + ty * 4 + i] = ok ? s[i][j] * ATT_SCALE : -3.4e38f;
        }
        __syncthreads();

        // online softmax: 4 threads per row; row = tid>>2, each scans 16 cols
        {
            int r = tid >> 2, sub = tid & 3;
            float mx = -3.4e38f;
#pragma unroll
            for (int cc = 0; cc < 16; cc++)
                mx = fmaxf(mx, St[(sub * 16 + cc) * TSTR + r]);
            mx = fmaxf(mx, __shfl_xor_sync(0xffffffffu, mx, 1));
            mx = fmaxf(mx, __shfl_xor_sync(0xffffffffu, mx, 2));
            float m_old = m_s[r];
            float m_new = fmaxf(m_old, mx);
            float psum = 0.f;
#pragma unroll
            for (int cc = 0; cc < 16; cc++) {
                int c = sub * 16 + cc;
                float arg = St[c * TSTR + r] - m_new;
                float p = __expf(fmaxf(arg, -80.f)) * (arg < -60.f ? 0.f : 1.f);
                St[c * TSTR + r] = p;
                psum += p;
            }
            psum += __shfl_xor_sync(0xffffffffu, psum, 1);
            psum += __shfl_xor_sync(0xffffffffu, psum, 2);
            if (sub == 0) {
                float al = __expf(fmaxf(m_old - m_new, -80.f)) * (m_old - m_new < -60.f ? 0.f : 1.f);
                a_s[r] = al;
                l_s[r] = l_s[r] * al + psum;
                m_s[r] = m_new;
            }
        }
        __syncthreads();

        // O = O*alpha + P @ V
        {
            float al[4];
#pragma unroll
            for (int i = 0; i < 4; i++) al[i] = a_s[ty * 4 + i];
#pragma unroll
            for (int i = 0; i < 4; i++)
#pragma unroll
                for (int j = 0; j < 4; j++) o[i][j] *= al[i];
#pragma unroll 8
            for (int kc = 0; kc < 64; kc++) {
                float4 pp = *(const float4*)&St[kc * TSTR + ty * 4];
                float4 vv = *(const float4*)&Vs[kc * TSTR + tx * 4];
                float pv[4] = {pp.x, pp.y, pp.z, pp.w};
                float vvv[4] = {vv.x, vv.y, vv.z, vv.w};
#pragma unroll
                for (int i = 0; i < 4; i++)
#pragma unroll
                    for (int j = 0; j < 4; j++) o[i][j] += pv[i] * vvv[j];
            }
        }
    }

    // finalize: divide by l, write to o_blocks [B*nb, H*HD]
#pragma unroll
    for (int i = 0; i < 4; i++) {
        int r = ty * 4 + i;
        float inv = 1.f / l_s[r];
        float4 vv = make_float4(o[i][0] * inv, o[i][1] * inv, o[i][2] * inv, o[i][3] * inv);
        *(float4*)&ob[(size_t)(b * NBLK + blk0 + r) * DD + h * HDIM + tx * 4] = vv;
    }
}

// ---------------- launcher ----------------
extern "C" void kernel_launch(void* const* d_in, const int* in_sizes, int n_in,
                              void* d_out, int out_size) {
    const float* x    = (const float*)d_in[0];
    const float* enc  = (const float*)d_in[1];
    const int*   mask = (const int*)d_in[2];
    const float* Wq   = (const float*)d_in[3];
    const float* Wk   = (const float*)d_in[4];
    const float* Wv   = (const float*)d_in[5];
    const float* Wo   = (const float*)d_in[6];
    float* out = (float*)d_out;

    float *pooled, *q, *k, *v, *ob;
    cudaGetSymbolAddress((void**)&pooled, g_pooled);
    cudaGetSymbolAddress((void**)&q, g_q);
    cudaGetSymbolAddress((void**)&k, g_k);
    cudaGetSymbolAddress((void**)&v, g_v);
    cudaGetSymbolAddress((void**)&ob, g_ob);

    // 1) pool decoder tokens into blocks
    pool_kernel<<<BB * NBLK, 256>>>(x, pooled);

    // 2) q projection: [1024,1024] @ [1024,1024] (64x64 tiles -> 256 blocks)
    sgemm_kernel<64, 64, 4, 4, false><<<dim3(DD / 64, BB * NBLK / 64), 256>>>(
        pooled, Wq, q, BB * NBLK, DD, DD);

    // 3) k,v projections: [8192,1024] @ [1024,256]
    sgemm_kernel<128, 128, 8, 8, false><<<dim3(KVW / 128, BB * SSS / 128), 256>>>(
        enc, Wk, k, BB * SSS, KVW, DD);
    sgemm_kernel<128, 128, 8, 8, false><<<dim3(KVW / 128, BB * SSS / 128), 256>>>(
        enc, Wv, v, BB * SSS, KVW, DD);

    // 4) fused flash attention
    int smem_bytes = (4 * 64 * TSTR + 3 * 64) * (int)sizeof(float) + 64 * (int)sizeof(int);
    cudaFuncSetAttribute(attn_kernel, cudaFuncAttributeMaxDynamicSharedMemorySize, smem_bytes);
    attn_kernel<<<dim3(NBLK / 64, HH, BB), 256, smem_bytes>>>(q, k, v, mask, ob);

    // 5) out projection fused with 16x token broadcast
    sgemm_kernel<64, 64, 4, 4, true><<<dim3(DD / 64, BB * NBLK / 64), 256>>>(
        ob, Wo, out, BB * NBLK, DD, DD);
}